// round 8
// baseline (speedup 1.0000x reference)
#include <cuda_runtime.h>
#include <cuda_bf16.h>
#include <math.h>

// Problem constants (shapes fixed by the dataset)
#define NN   20000
#define EE   320000
#define PP   50000
#define LL   20
#define INF_ 128
#define HH   64
#define CW   384   // fused node-GEMM output width: [HW(64) | HOm(64) | A1(128) | B1(128)]
#define NBLK 79    // ceildiv(NN,256)

// ---------------- scratch (device globals; no cudaMalloc allowed) ----------------
__device__ int   g_cnt[NN];
__device__ float g_dinv[NN];
__device__ int   g_scan1[NN];
__device__ int   g_bsum[256];
__device__ int   g_offs[NN + 1];
__device__ int   g_fill[NN];
__device__ int   g_csr_row[EE + NN];
__device__ float g_csr_norm[EE + NN];
__device__ float g_H[NN * HH];
__device__ float g_C[(size_t)NN * CW];
__device__ float g_dH[NN * HH];
__device__ float g_afv[NN];
__device__ float g_bfv[NN];
__device__ float g_r[(size_t)PP * 2 * HH];
__device__ float g_Wcat[HH * CW];

static inline int ceildiv(int a, int b) { return (a + b - 1) / b; }

// ---------------- setup kernels ----------------

// Wcat[k][0:64]   = W_s    = 0.5*(Ws_raw + Ws_raw^T)
// Wcat[k][64:128] = Om_as  = Omega - Omega^T
// Wcat[k][128:256]= W_fc1 top rows   (k in 0..63)
// Wcat[k][256:384]= W_fc1 bottom rows (k+64)
// NOTE: writes g_Wcat directly (device symbol). Passing a __device__ global as a
// host-side kernel argument passes the HOST shadow address (silently writable via
// ATS on GB300) — that was the round-2..7 bug.
__global__ __launch_bounds__(256) void build_wcat(const float* __restrict__ Omega,
                                                  const float* __restrict__ Wsr,
                                                  const float* __restrict__ Wfc1) {
    int i = blockIdx.x * blockDim.x + threadIdx.x;
    if (i >= HH * CW) return;
    int k = i / CW, j = i % CW;
    float v;
    if (j < 64)        v = 0.5f * (Wsr[k * 64 + j] + Wsr[j * 64 + k]);
    else if (j < 128)  { int jj = j - 64; v = Omega[k * 64 + jj] - Omega[jj * 64 + k]; }
    else if (j < 256)  { int jj = j - 128; v = Wfc1[k * 128 + jj]; }
    else               { int jj = j - 256; v = Wfc1[(64 + k) * 128 + jj]; }
    g_Wcat[i] = v;
}

__global__ __launch_bounds__(256) void init_cnt(int N) {
    int i = blockIdx.x * blockDim.x + threadIdx.x;
    if (i < N) g_cnt[i] = 1;  // self loop
}

__global__ __launch_bounds__(256) void count_edges(const int* __restrict__ ei, int E) {
    int i = blockIdx.x * blockDim.x + threadIdx.x;
    if (i < E) atomicAdd(&g_cnt[ei[E + i]], 1);
}

__global__ __launch_bounds__(256) void compute_dinv(int N) {
    int i = blockIdx.x * blockDim.x + threadIdx.x;
    if (i < N) { g_dinv[i] = rsqrtf((float)g_cnt[i]); g_fill[i] = 0; }
}

// ---- multi-block scan (all 256-thread launches) ----
__global__ __launch_bounds__(256) void scan_pass1(int N) {
    __shared__ int buf[256];
    int tid = threadIdx.x;
    int i = blockIdx.x * 256 + tid;
    buf[tid] = (i < N) ? g_cnt[i] : 0;
    __syncthreads();
#pragma unroll
    for (int off = 1; off < 256; off <<= 1) {
        int t = (tid >= off) ? buf[tid - off] : 0;
        __syncthreads();
        buf[tid] += t;
        __syncthreads();
    }
    if (i < N) g_scan1[i] = buf[tid];
    if (tid == 255) g_bsum[blockIdx.x] = buf[255];
}

__global__ __launch_bounds__(256) void scan_pass2(int nb) {
    __shared__ int buf[256];
    int tid = threadIdx.x;
    buf[tid] = (tid < nb) ? g_bsum[tid] : 0;
    __syncthreads();
#pragma unroll
    for (int off = 1; off < 256; off <<= 1) {
        int t = (tid >= off) ? buf[tid - off] : 0;
        __syncthreads();
        buf[tid] += t;
        __syncthreads();
    }
    if (tid < nb) g_bsum[tid] = buf[tid];
}

__global__ __launch_bounds__(256) void scan_pass3(int N) {
    int i = blockIdx.x * 256 + threadIdx.x;
    if (i < N) {
        int pre = (blockIdx.x > 0) ? g_bsum[blockIdx.x - 1] : 0;
        g_offs[i + 1] = pre + g_scan1[i];
    }
    if (i == 0) g_offs[0] = 0;
}

__global__ __launch_bounds__(256) void fill_csr(const int* __restrict__ ei, int E, int N) {
    int i = blockIdx.x * blockDim.x + threadIdx.x;
    if (i < E) {
        int rr = ei[i];
        int c  = ei[E + i];
        int pos = g_offs[c] + atomicAdd(&g_fill[c], 1);
        g_csr_row[pos]  = rr;
        g_csr_norm[pos] = g_dinv[rr] * g_dinv[c];
    } else if (i < E + N) {
        int v = i - E;
        int pos = g_offs[v] + atomicAdd(&g_fill[v], 1);
        g_csr_row[pos] = v;
        float d = g_dinv[v];
        g_csr_norm[pos] = d * d;
    }
}

// ---------------- encoder: H = relu(x @ W_enc), x:(N,128), W:(128,64) ----------------
__global__ __launch_bounds__(256) void enc_gemm(const float* __restrict__ x,
                                                const float* __restrict__ Wenc,
                                                int N) {
    __shared__ float Ws[INF_][HH];   // 32 KB
    __shared__ float Xs[16][INF_];   //  8 KB
    int tid = threadIdx.x;
    int rowBase = blockIdx.x * 16;
    for (int i = tid; i < INF_ * HH; i += 256) Ws[i / HH][i % HH] = Wenc[i];
    for (int i = tid; i < 16 * INF_; i += 256) {
        int r = i >> 7, k = i & 127;
        int gr = rowBase + r;
        Xs[r][k] = (gr < N) ? x[(size_t)gr * INF_ + k] : 0.f;
    }
    __syncthreads();
    int tx = tid & 31;   // cols tx, tx+32
    int ty = tid >> 5;   // rows ty*2, ty*2+1
    float acc00 = 0.f, acc01 = 0.f, acc10 = 0.f, acc11 = 0.f;
#pragma unroll 8
    for (int k = 0; k < INF_; k++) {
        float b0 = Ws[k][tx], b1 = Ws[k][tx + 32];
        float a0 = Xs[ty * 2][k], a1 = Xs[ty * 2 + 1][k];
        acc00 = fmaf(a0, b0, acc00);
        acc01 = fmaf(a0, b1, acc01);
        acc10 = fmaf(a1, b0, acc10);
        acc11 = fmaf(a1, b1, acc11);
    }
    int gr0 = rowBase + ty * 2;
    int gr1 = gr0 + 1;
    if (gr0 < N) {
        g_H[gr0 * HH + tx]      = fmaxf(acc00, 0.f);
        g_H[gr0 * HH + tx + 32] = fmaxf(acc01, 0.f);
    }
    if (gr1 < N) {
        g_H[gr1 * HH + tx]      = fmaxf(acc10, 0.f);
        g_H[gr1 * HH + tx + 32] = fmaxf(acc11, 0.f);
    }
}

// ---------------- r init: r[p] = [H[src], H[dst]], ts = 0 ----------------
__global__ __launch_bounds__(256) void init_r(const int* __restrict__ pairs,
                                              float* __restrict__ ts, int P) {
    int w = (blockIdx.x * blockDim.x + threadIdx.x) >> 5;
    int lane = threadIdx.x & 31;
    if (w >= P) return;
    int src = pairs[2 * w], dst = pairs[2 * w + 1];
    float* rp = g_r + (size_t)w * 128;
    rp[lane]       = g_H[src * HH + lane];
    rp[lane + 32]  = g_H[src * HH + lane + 32];
    rp[lane + 64]  = g_H[dst * HH + lane];
    rp[lane + 96]  = g_H[dst * HH + lane + 32];
    if (lane == 0) ts[w] = 0.f;
}

// ---------------- step K1: C = H @ Wcat  (N x 384), tiled fp32 GEMM ----------------
__global__ __launch_bounds__(256) void step_gemm(int N) {
    __shared__ float Ws[HH][128];   // 32 KB
    __shared__ float Hs[32][HH];    //  8 KB
    int tid = threadIdx.x;
    int rowBase = blockIdx.x * 32;
    int colBase = blockIdx.y * 128;
    for (int i = tid; i < HH * 128; i += 256) {
        int k = i >> 7, j = i & 127;
        Ws[k][j] = g_Wcat[k * CW + colBase + j];
    }
    for (int i = tid; i < 32 * HH; i += 256) {
        int r = i / HH, k = i % HH;
        int gr = rowBase + r;
        Hs[r][k] = (gr < N) ? g_H[gr * HH + k] : 0.f;
    }
    __syncthreads();
    int tx = tid & 31;
    int ty = tid >> 5;
    float acc[4][4];
#pragma unroll
    for (int i = 0; i < 4; i++)
#pragma unroll
        for (int j = 0; j < 4; j++) acc[i][j] = 0.f;
#pragma unroll 4
    for (int k = 0; k < HH; k++) {
        const float4* wrow = reinterpret_cast<const float4*>(&Ws[k][0]);
        float4 b = wrow[tx];
#pragma unroll
        for (int i = 0; i < 4; i++) {
            float a = Hs[ty * 4 + i][k];
            acc[i][0] = fmaf(a, b.x, acc[i][0]);
            acc[i][1] = fmaf(a, b.y, acc[i][1]);
            acc[i][2] = fmaf(a, b.z, acc[i][2]);
            acc[i][3] = fmaf(a, b.w, acc[i][3]);
        }
    }
#pragma unroll
    for (int i = 0; i < 4; i++) {
        int gr = rowBase + ty * 4 + i;
        if (gr < N) {
            float4 v = make_float4(acc[i][0], acc[i][1], acc[i][2], acc[i][3]);
            *reinterpret_cast<float4*>(&g_C[(size_t)gr * CW + colBase + tx * 4]) = v;
        }
    }
}

// ---------------- step K2: warp-per-node CSR gather + dH + H update + fv dots ----------------
__global__ __launch_bounds__(256) void step_node(const float* __restrict__ Wfv, int N) {
    int w = (blockIdx.x * blockDim.x + threadIdx.x) >> 5;
    int lane = threadIdx.x & 31;
    if (w >= N) return;
    int v = w;
    int s = g_offs[v], e = g_offs[v + 1];
    float sym0 = 0.f, sym1 = 0.f;
    for (int i = s; i < e; i++) {
        int rr = g_csr_row[i];
        float nm = g_csr_norm[i];
        const float* hw = g_C + (size_t)rr * CW;
        sym0 = fmaf(nm, hw[lane], sym0);
        sym1 = fmaf(nm, hw[lane + 32], sym1);
    }
    const float* crow = g_C + (size_t)v * CW;
    float pre0 = sym0 - fmaxf(crow[64 + lane], 0.f);
    float pre1 = sym1 - fmaxf(crow[96 + lane], 0.f);
    float dh0 = fmaxf(tanhf(pre0), 0.f);
    float dh1 = fmaxf(tanhf(pre1), 0.f);
    float h0 = g_H[v * HH + lane];
    float h1 = g_H[v * HH + lane + 32];
    // fv dots on OLD H
    float pa = h0 * Wfv[lane] + h1 * Wfv[lane + 32];
    float pb = h0 * Wfv[64 + lane] + h1 * Wfv[96 + lane];
#pragma unroll
    for (int o = 16; o; o >>= 1) {
        pa += __shfl_down_sync(0xffffffffu, pa, o);
        pb += __shfl_down_sync(0xffffffffu, pb, o);
    }
    if (lane == 0) { g_afv[v] = pa; g_bfv[v] = pb; }
    g_dH[v * HH + lane]      = dh0;
    g_dH[v * HH + lane + 32] = dh1;
    g_H[v * HH + lane]       = h0 + dh0;
    g_H[v * HH + lane + 32]  = h1 + dh1;
}

// ---------------- step K3: warp-per-pair gate + r/ts update ----------------
__global__ __launch_bounds__(256) void step_pair(const int* __restrict__ pairs,
                                                 const float* __restrict__ gum,   // (P,2) slice
                                                 const float* __restrict__ Wfc2,  // (128,2)
                                                 float* __restrict__ ts, int P) {
    int w = (blockIdx.x * blockDim.x + threadIdx.x) >> 5;
    int lane = threadIdx.x & 31;
    if (w >= P) return;
    int p = w;
    int src = pairs[2 * p], dst = pairs[2 * p + 1];
    const float* A = g_C + (size_t)src * CW + 128;
    const float* B = g_C + (size_t)dst * CW + 256;
    float l0 = 0.f, l1 = 0.f;
#pragma unroll
    for (int q = 0; q < 4; q++) {
        int j = lane + q * 32;
        float h = fmaxf(A[j] + B[j], 0.f);
        l0 = fmaf(h, Wfc2[2 * j], l0);
        l1 = fmaf(h, Wfc2[2 * j + 1], l1);
    }
#pragma unroll
    for (int o = 16; o; o >>= 1) {
        l0 += __shfl_down_sync(0xffffffffu, l0, o);
        l1 += __shfl_down_sync(0xffffffffu, l1, o);
    }
    l0 = __shfl_sync(0xffffffffu, l0, 0);
    l1 = __shfl_sync(0xffffffffu, l1, 0);
    float xfv = g_afv[src] + g_bfv[dst];
    float sp = (xfv > 20.f) ? xfv : log1pf(__expf(xfv));
    float nu = sp + 1.0f;   // NU0
    float gz0 = gum[2 * (size_t)p];
    float gz1 = gum[2 * (size_t)p + 1];
    float z0 = (l0 + gz0) / nu;
    float z1 = (l1 + gz1) / nu;
    float tau = 1.f / (1.f + __expf(z1 - z0));
    const float* ds = g_dH + (size_t)src * HH;
    const float* dd = g_dH + (size_t)dst * HH;
    float* rp = g_r + (size_t)p * 128;
    rp[lane]      = fmaf(tau, ds[lane],      rp[lane]);
    rp[lane + 32] = fmaf(tau, ds[lane + 32], rp[lane + 32]);
    rp[lane + 64] = fmaf(tau, dd[lane],      rp[lane + 64]);
    rp[lane + 96] = fmaf(tau, dd[lane + 32], rp[lane + 96]);
    if (lane == 0) ts[p] += tau;
}

// ---------------- final: scores = (relu(r @ W_p1) @ W_p2)[:,0] ----------------
__global__ __launch_bounds__(256) void final_scores(const float* __restrict__ Wp1,
                                                    const float* __restrict__ Wp2,
                                                    float* __restrict__ scores, int P) {
    __shared__ float W1s[128 * 64];  // 32 KB
    __shared__ float W2s[64];
    int tid = threadIdx.x;
    for (int i = tid; i < 128 * 64; i += 256) W1s[i] = Wp1[i];
    if (tid < 64) W2s[tid] = Wp2[tid];
    __syncthreads();
    int lane = tid & 31, w = tid >> 5;
    for (int p = blockIdx.x * 8 + w; p < P; p += gridDim.x * 8) {
        const float* rp = g_r + (size_t)p * 128;
        float rv[4];
#pragma unroll
        for (int q = 0; q < 4; q++) rv[q] = rp[lane + q * 32];
        float h0 = 0.f, h1 = 0.f;
#pragma unroll
        for (int k = 0; k < 128; k++) {
            float rk = __shfl_sync(0xffffffffu, rv[k >> 5], k & 31);
            h0 = fmaf(rk, W1s[k * 64 + lane], h0);
            h1 = fmaf(rk, W1s[k * 64 + lane + 32], h1);
        }
        float s = fmaxf(h0, 0.f) * W2s[lane] + fmaxf(h1, 0.f) * W2s[lane + 32];
#pragma unroll
        for (int o = 16; o; o >>= 1) s += __shfl_down_sync(0xffffffffu, s, o);
        if (lane == 0) scores[p] = s;
    }
}

// ---------------- launch ----------------
extern "C" void kernel_launch(void* const* d_in, const int* in_sizes, int n_in,
                              void* d_out, int out_size) {
    // Size-based input resolution (robust to metadata ordering), positional fallback.
    const int want[12] = {
        NN * INF_,       // x          2,560,000
        2 * EE,          // edge_index   640,000
        2 * PP,          // pairs        100,000
        LL * PP * 2,     // gumbel     2,000,000
        INF_ * HH,       // W_enc          8,192
        HH * HH,         // Omega          4,096
        HH * HH,         // Ws_raw         4,096
        2 * HH * 2 * HH, // W_fc1         16,384
        2 * HH * 2,      // W_fc2            256
        2 * HH,          // W_fv             128
        2 * HH * HH,     // W_p1           8,192
        HH               // W_p2              64
    };
    const void* res[12];
    bool ok = (n_in == 12);
    if (ok) {
        bool used[12] = {false};
        for (int s = 0; s < 12 && ok; s++) {
            int found = -1;
            for (int i = 0; i < 12; i++) {
                if (!used[i] && in_sizes[i] == want[s]) { found = i; break; }
            }
            if (found < 0) { ok = false; break; }
            used[found] = true;
            res[s] = d_in[found];
        }
    }
    if (!ok) { for (int i = 0; i < 12 && i < n_in; i++) res[i] = d_in[i]; }

    const float* x    = (const float*)res[0];
    const int*   ei   = (const int*)res[1];
    const int*   prs  = (const int*)res[2];
    const float* gum  = (const float*)res[3];
    const float* Wenc = (const float*)res[4];
    const float* Omeg = (const float*)res[5];
    const float* Wsr  = (const float*)res[6];
    const float* Wfc1 = (const float*)res[7];
    const float* Wfc2 = (const float*)res[8];
    const float* Wfv  = (const float*)res[9];
    const float* Wp1  = (const float*)res[10];
    const float* Wp2  = (const float*)res[11];
    float* out = (float*)d_out;

    const int N = NN, E = EE, P = PP, L = LL;

    float* scores = out;       // [0, P)
    float* ts     = out + P;   // [P, 2P)

    // setup
    build_wcat<<<ceildiv(HH * CW, 256), 256>>>(Omeg, Wsr, Wfc1);
    init_cnt<<<ceildiv(N, 256), 256>>>(N);
    count_edges<<<ceildiv(E, 256), 256>>>(ei, E);
    compute_dinv<<<ceildiv(N, 256), 256>>>(N);
    scan_pass1<<<NBLK, 256>>>(N);
    scan_pass2<<<1, 256>>>(NBLK);
    scan_pass3<<<NBLK, 256>>>(N);
    fill_csr<<<ceildiv(E + N, 256), 256>>>(ei, E, N);

    // encoder + r init
    enc_gemm<<<ceildiv(N, 16), 256>>>(x, Wenc, N);
    init_r<<<ceildiv(P * 32, 256), 256>>>(prs, ts, P);

    // 20 scan steps
    dim3 g1(ceildiv(N, 32), 3);
    for (int step = 0; step < L; step++) {
        step_gemm<<<g1, 256>>>(N);
        step_node<<<ceildiv(N * 32, 256), 256>>>(Wfv, N);
        step_pair<<<ceildiv(P * 32, 256), 256>>>(prs, gum + (size_t)step * P * 2, Wfc2, ts, P);
    }

    final_scores<<<1480, 256>>>(Wp1, Wp2, scores, P);
}